// round 1
// baseline (speedup 1.0000x reference)
#include <cuda_runtime.h>
#include <math.h>

#define Bsz 2
#define Lsz 2048
#define Dsz 1024
#define Hn  16
#define HDs 64
#define KTOPn 409
#define BHn (Bsz*Hn)
#define SCALE 0.125f

// ---------------- scratch (device globals: allocation-free rule) ----------------
__device__ float g_Q[Bsz*Lsz*Dsz];
__device__ float g_K[Bsz*Lsz*Dsz];
__device__ float g_V[Bsz*Lsz*Dsz];
__device__ float g_A[Bsz*Lsz*Dsz];       // attention output, [B,L,H*HD]
__device__ float g_norm[BHn*Lsz];
__device__ int   g_sel[BHn*KTOPn];
__device__ float g_part[Bsz*32*Dsz];
__device__ float g_vmean[Bsz*Dsz];

// ---------------- SGEMM: C[M,N] = A[M,K] * W[N,K]^T + bias[N] -------------------
// 128x128 tile, BK=16, 256 threads, 8x8 per thread.
__global__ __launch_bounds__(256, 2)
void sgemm_nt(const float* __restrict__ A, const float* __restrict__ W,
              const float* __restrict__ bias, float* __restrict__ C,
              int M, int N, int K) {
    __shared__ float As[16][132];
    __shared__ float Bs[16][132];
    int tid = threadIdx.x;
    int bm = blockIdx.y * 128, bn = blockIdx.x * 128;
    int tx = tid & 15, ty = tid >> 4;

    float acc[8][8];
#pragma unroll
    for (int i = 0; i < 8; i++)
#pragma unroll
        for (int j = 0; j < 8; j++) acc[i][j] = 0.f;

    for (int kk = 0; kk < K; kk += 16) {
#pragma unroll
        for (int ld = 0; ld < 2; ld++) {
            int idx = tid + ld * 256;          // 0..511
            int r  = idx >> 2;                 // 0..127
            int c4 = (idx & 3) * 4;            // 0,4,8,12
            float4 av = *(const float4*)&A[(size_t)(bm + r) * K + kk + c4];
            As[c4+0][r] = av.x; As[c4+1][r] = av.y; As[c4+2][r] = av.z; As[c4+3][r] = av.w;
            float4 wv = *(const float4*)&W[(size_t)(bn + r) * K + kk + c4];
            Bs[c4+0][r] = wv.x; Bs[c4+1][r] = wv.y; Bs[c4+2][r] = wv.z; Bs[c4+3][r] = wv.w;
        }
        __syncthreads();
#pragma unroll
        for (int k = 0; k < 16; k++) {
            float af[8], bf[8];
            *(float4*)&af[0] = *(float4*)&As[k][ty*8];
            *(float4*)&af[4] = *(float4*)&As[k][ty*8+4];
            *(float4*)&bf[0] = *(float4*)&Bs[k][tx*8];
            *(float4*)&bf[4] = *(float4*)&Bs[k][tx*8+4];
#pragma unroll
            for (int i = 0; i < 8; i++)
#pragma unroll
                for (int j = 0; j < 8; j++) acc[i][j] += af[i] * bf[j];
        }
        __syncthreads();
    }

    float bfrag[8];
#pragma unroll
    for (int j = 0; j < 8; j++) bfrag[j] = bias[bn + tx*8 + j];
#pragma unroll
    for (int i = 0; i < 8; i++) {
        int row = bm + ty*8 + i;
#pragma unroll
        for (int j = 0; j < 8; j += 4) {
            float4 o;
            o.x = acc[i][j+0] + bfrag[j+0];
            o.y = acc[i][j+1] + bfrag[j+1];
            o.z = acc[i][j+2] + bfrag[j+2];
            o.w = acc[i][j+3] + bfrag[j+3];
            *(float4*)&C[(size_t)row * N + bn + tx*8 + j] = o;
        }
    }
}

// ---------------- per-(b,h,l) squared L2 norm of q -----------------------------
__global__ void qnorm_kernel(const float* __restrict__ Q, float* __restrict__ norms) {
    int gw = blockIdx.x * 8 + (threadIdx.x >> 5);
    int lane = threadIdx.x & 31;
    if (gw >= BHn * Lsz) return;
    int l = gw % Lsz;
    int h = (gw / Lsz) % Hn;
    int b = gw / (Lsz * Hn);
    const float* row = Q + (size_t)(b * Lsz + l) * Dsz + h * HDs;
    float v0 = row[lane], v1 = row[lane + 32];
    float ss = v0*v0 + v1*v1;
#pragma unroll
    for (int o = 16; o; o >>= 1) ss += __shfl_xor_sync(0xffffffffu, ss, o);
    if (lane == 0) norms[(b * Hn + h) * Lsz + l] = ss;
}

// ---------------- exact top-k per (b,h): bitonic sort + tie handling -----------
__global__ void topk_kernel(const float* __restrict__ norms, int* __restrict__ sel) {
    int bh = blockIdx.x;
    __shared__ float s[Lsz];
    __shared__ int cnt_out;
    __shared__ int cnt_gt;
    const float* nb = norms + (size_t)bh * Lsz;
    int tid = threadIdx.x;
    for (int i = tid; i < Lsz; i += 256) s[i] = nb[i];
    __syncthreads();
    // bitonic sort, descending
    for (int ksz = 2; ksz <= Lsz; ksz <<= 1) {
        for (int j = ksz >> 1; j > 0; j >>= 1) {
            for (int idx = tid; idx < Lsz; idx += 256) {
                int ixj = idx ^ j;
                if (ixj > idx) {
                    bool desc = ((idx & ksz) == 0);
                    float a = s[idx], bb = s[ixj];
                    bool sw = desc ? (a < bb) : (a > bb);
                    if (sw) { s[idx] = bb; s[ixj] = a; }
                }
            }
            __syncthreads();
        }
    }
    float t = s[KTOPn - 1];
    if (tid == 0) { cnt_out = 0; cnt_gt = 0; }
    __syncthreads();
    int lc = 0;
    for (int i = tid; i < Lsz; i += 256) lc += (nb[i] > t) ? 1 : 0;
    atomicAdd(&cnt_gt, lc);
    __syncthreads();
    int need = KTOPn - cnt_gt;   // how many elements equal to t get in (lowest indices)
    for (int i = tid; i < Lsz; i += 256) {
        float v = nb[i];
        bool pick = false;
        if (v > t) pick = true;
        else if (v == t) {
            int eqb = 0;
            for (int jj = 0; jj < i; jj++) eqb += (nb[jj] == t) ? 1 : 0;
            pick = (eqb < need);
        }
        if (pick) {
            int p = atomicAdd(&cnt_out, 1);
            sel[(size_t)bh * KTOPn + p] = i;
        }
    }
}

// ---------------- V column means: partial sums then reduce ---------------------
__global__ void vpartial_kernel(const float* __restrict__ V, float* __restrict__ part) {
    int b = blockIdx.x >> 5, c = blockIdx.x & 31;
    int d = threadIdx.x; // 0..1023
    float sum = 0.f;
#pragma unroll 4
    for (int r = 0; r < 64; r++)
        sum += V[(size_t)(b * Lsz + c * 64 + r) * Dsz + d];
    part[(size_t)(b * 32 + c) * Dsz + d] = sum;
}

__global__ void vmean_kernel(const float* __restrict__ part, float* __restrict__ vm) {
    int i = blockIdx.x * 256 + threadIdx.x;
    if (i >= Bsz * Dsz) return;
    int b = i / Dsz, d = i % Dsz;
    float sum = 0.f;
#pragma unroll
    for (int c = 0; c < 32; c++) sum += part[(size_t)(b * 32 + c) * Dsz + d];
    vm[i] = sum * (1.0f / Lsz);
}

// Fill every row of the attention output with vmean; selected rows overwritten later.
__global__ void fill_kernel(const float* __restrict__ vm, float* __restrict__ attn) {
    size_t i = (size_t)blockIdx.x * 256 + threadIdx.x;
    if (i >= (size_t)Bsz * Lsz * Dsz) return;
    int d = (int)(i % Dsz);
    int b = (int)(i / ((size_t)Lsz * Dsz));
    attn[i] = vm[b * Dsz + d];
}

// ---------------- flash attention over selected queries only -------------------
// grid: (ceil(KTOP/32), B*H); 256 threads = (ty 0..15) x (tx 0..15)
// thread owns q rows {ty*2, ty*2+1}; scores cols tx*4..+3; output hd tx*4..+3
__global__ __launch_bounds__(256)
void attn_kernel(const float* __restrict__ Q, const float* __restrict__ K,
                 const float* __restrict__ V, const int* __restrict__ sel,
                 float* __restrict__ out) {
    __shared__ float Qs[32][64];      // broadcast reads only
    __shared__ float buf[64][68];     // Kt[d][key] for scores, then V[key][hd] for PV
    __shared__ float Ps[32][64];      // probs
    __shared__ int   sidx[32];

    int bh = blockIdx.y;
    int b = bh / Hn, h = bh % Hn;
    int qbase = blockIdx.x * 32;
    int tid = threadIdx.x;
    int tx = tid & 15, ty = tid >> 4;

    if (tid < 32) {
        int qi = qbase + tid;
        sidx[tid] = (qi < KTOPn) ? sel[(size_t)bh * KTOPn + qi] : -1;
    }
    __syncthreads();
    // load selected Q rows (zeros for inactive slots)
    for (int i = tid; i < 32 * 16; i += 256) {
        int r = i >> 4, c4 = (i & 15) * 4;
        float4 v = make_float4(0.f, 0.f, 0.f, 0.f);
        int sl = sidx[r];
        if (sl >= 0)
            v = *(const float4*)&Q[(size_t)(b * Lsz + sl) * Dsz + h * HDs + c4];
        *(float4*)&Qs[r][c4] = v;
    }

    float m_i[2] = { -INFINITY, -INFINITY };
    float l_i[2] = { 0.f, 0.f };
    float acc[2][4] = { {0.f,0.f,0.f,0.f}, {0.f,0.f,0.f,0.f} };

    for (int kt = 0; kt < Lsz; kt += 64) {
        __syncthreads();  // prior PV done reading buf (and Qs store visible on 1st iter)
        // load K tile transposed: buf[d][key]
        for (int i = tid; i < 64 * 16; i += 256) {
            int r = i >> 4, c4 = (i & 15) * 4;
            float4 kv = *(const float4*)&K[(size_t)(b * Lsz + kt + r) * Dsz + h * HDs + c4];
            buf[c4+0][r] = kv.x; buf[c4+1][r] = kv.y; buf[c4+2][r] = kv.z; buf[c4+3][r] = kv.w;
        }
        __syncthreads();

        // scores: s[i][j] = q_{ty*2+i} . k_{tx*4+j}
        float s[2][4] = { {0,0,0,0}, {0,0,0,0} };
#pragma unroll
        for (int dq = 0; dq < 16; dq++) {
            float4 q0 = *(float4*)&Qs[ty*2+0][dq*4];
            float4 q1 = *(float4*)&Qs[ty*2+1][dq*4];
#pragma unroll
            for (int dd = 0; dd < 4; dd++) {
                float4 kv = *(float4*)&buf[dq*4+dd][tx*4];
                float qa = (&q0.x)[dd], qb = (&q1.x)[dd];
                s[0][0] += qa*kv.x; s[0][1] += qa*kv.y; s[0][2] += qa*kv.z; s[0][3] += qa*kv.w;
                s[1][0] += qb*kv.x; s[1][1] += qb*kv.y; s[1][2] += qb*kv.z; s[1][3] += qb*kv.w;
            }
        }

        float corr[2];
#pragma unroll
        for (int i = 0; i < 2; i++) {
#pragma unroll
            for (int j = 0; j < 4; j++) s[i][j] *= SCALE;
            float m = fmaxf(fmaxf(s[i][0], s[i][1]), fmaxf(s[i][2], s[i][3]));
            m = fmaxf(m, __shfl_xor_sync(0xffffffffu, m, 1, 16));
            m = fmaxf(m, __shfl_xor_sync(0xffffffffu, m, 2, 16));
            m = fmaxf(m, __shfl_xor_sync(0xffffffffu, m, 4, 16));
            m = fmaxf(m, __shfl_xor_sync(0xffffffffu, m, 8, 16));
            float mnew = fmaxf(m_i[i], m);
            float p[4], ps = 0.f;
#pragma unroll
            for (int j = 0; j < 4; j++) {
                p[j] = __expf(s[i][j] - mnew);
                Ps[ty*2+i][tx*4+j] = p[j];
                ps += p[j];
            }
            ps += __shfl_xor_sync(0xffffffffu, ps, 1, 16);
            ps += __shfl_xor_sync(0xffffffffu, ps, 2, 16);
            ps += __shfl_xor_sync(0xffffffffu, ps, 4, 16);
            ps += __shfl_xor_sync(0xffffffffu, ps, 8, 16);
            corr[i] = __expf(m_i[i] - mnew);
            l_i[i] = l_i[i] * corr[i] + ps;
            m_i[i] = mnew;
        }

        __syncthreads();  // everyone done reading K from buf
        // load V tile row-major: buf[key][hd]
        for (int i = tid; i < 64 * 16; i += 256) {
            int r = i >> 4, c4 = (i & 15) * 4;
            float4 vv = *(const float4*)&V[(size_t)(b * Lsz + kt + r) * Dsz + h * HDs + c4];
            *(float4*)&buf[r][c4] = vv;
        }
        __syncthreads();  // V loaded; also makes Ps visible block-wide (only warp-local needed)

#pragma unroll
        for (int i = 0; i < 2; i++)
#pragma unroll
            for (int j = 0; j < 4; j++) acc[i][j] *= corr[i];

#pragma unroll
        for (int kq = 0; kq < 16; kq++) {
            float4 p0 = *(float4*)&Ps[ty*2+0][kq*4];
            float4 p1 = *(float4*)&Ps[ty*2+1][kq*4];
#pragma unroll
            for (int dd = 0; dd < 4; dd++) {
                float4 vv = *(float4*)&buf[kq*4+dd][tx*4];
                float pa = (&p0.x)[dd], pb = (&p1.x)[dd];
                acc[0][0] += pa*vv.x; acc[0][1] += pa*vv.y; acc[0][2] += pa*vv.z; acc[0][3] += pa*vv.w;
                acc[1][0] += pb*vv.x; acc[1][1] += pb*vv.y; acc[1][2] += pb*vv.z; acc[1][3] += pb*vv.w;
            }
        }
    }

#pragma unroll
    for (int i = 0; i < 2; i++) {
        int q = ty*2 + i;
        if (qbase + q < KTOPn) {
            int sl = sidx[q];
            float inv = 1.0f / l_i[i];
            float4 o = make_float4(acc[i][0]*inv, acc[i][1]*inv, acc[i][2]*inv, acc[i][3]*inv);
            *(float4*)&out[(size_t)(b * Lsz + sl) * Dsz + h * HDs + tx*4] = o;
        }
    }
}

// ---------------- launch -------------------------------------------------------
extern "C" void kernel_launch(void* const* d_in, const int* in_sizes, int n_in,
                              void* d_out, int out_size) {
    const float* x  = (const float*)d_in[0];
    const float* Wq = (const float*)d_in[1];
    const float* bq = (const float*)d_in[2];
    const float* Wk = (const float*)d_in[3];
    const float* bk = (const float*)d_in[4];
    const float* Wv = (const float*)d_in[5];
    const float* bv = (const float*)d_in[6];
    const float* Wo = (const float*)d_in[7];
    const float* bo = (const float*)d_in[8];
    float* out = (float*)d_out;

    float *pQ, *pK, *pV, *pA, *pN, *pPart, *pM;
    int* pS;
    cudaGetSymbolAddress((void**)&pQ, g_Q);
    cudaGetSymbolAddress((void**)&pK, g_K);
    cudaGetSymbolAddress((void**)&pV, g_V);
    cudaGetSymbolAddress((void**)&pA, g_A);
    cudaGetSymbolAddress((void**)&pN, g_norm);
    cudaGetSymbolAddress((void**)&pS, g_sel);
    cudaGetSymbolAddress((void**)&pPart, g_part);
    cudaGetSymbolAddress((void**)&pM, g_vmean);

    const int M = Bsz * Lsz;   // 4096
    dim3 gemm_grid(Dsz / 128, M / 128);

    sgemm_nt<<<gemm_grid, 256>>>(x, Wq, bq, pQ, M, Dsz, Dsz);
    sgemm_nt<<<gemm_grid, 256>>>(x, Wk, bk, pK, M, Dsz, Dsz);
    sgemm_nt<<<gemm_grid, 256>>>(x, Wv, bv, pV, M, Dsz, Dsz);

    qnorm_kernel<<<(BHn * Lsz) / 8, 256>>>(pQ, pN);
    topk_kernel<<<BHn, 256>>>(pN, pS);

    vpartial_kernel<<<Bsz * 32, 1024>>>(pV, pPart);
    vmean_kernel<<<(Bsz * Dsz + 255) / 256, 256>>>(pPart, pM);
    fill_kernel<<<(Bsz * Lsz * Dsz) / 256, 256>>>(pM, pA);

    attn_kernel<<<dim3((KTOPn + 31) / 32, BHn), 256>>>(pQ, pK, pV, pS, pA);

    sgemm_nt<<<gemm_grid, 256>>>(pA, Wo, bo, out, M, Dsz, Dsz);
}

// round 3
// speedup vs baseline: 1.1457x; 1.1457x over previous
#include <cuda_runtime.h>
#include <math.h>

#define Bsz 2
#define Lsz 2048
#define Dsz 1024
#define Hn  16
#define HDs 64
#define KTOPn 409
#define BHn (Bsz*Hn)
#define SCALE 0.125f

// ---------------- scratch (device globals: allocation-free rule) ----------------
__device__ float g_Q[Bsz*Lsz*Dsz];
__device__ float g_K[Bsz*Lsz*Dsz];
__device__ float g_V[Bsz*Lsz*Dsz];
__device__ float g_A[Bsz*Lsz*Dsz];       // attention output, [B,L,H*HD]
__device__ float g_norm[BHn*Lsz];
__device__ int   g_sel[BHn*KTOPn];
__device__ float g_part[Bsz*32*Dsz];
__device__ float g_vmean[Bsz*Dsz];

// ------------- 3xTF32 tensor-core GEMM: C = A[M,K] * W[N,K]^T + bias -----------
// 128x128 tile, BK=16, 256 threads (8 warps as 4x2), mma.sync.m16n8k8.tf32.
// Each fp32 split hi=tf32(x), lo=tf32(x-hi); c += hi*hi + hi*lo + lo*hi.
// Dropped lo*lo ~ 2^-22 relative: near-fp32 accuracy (needed: top-k selection
// is discontinuous in Q — single-pass tf32 flips selections and fails).
// Smem row pad to 20 floats: row stride 20 == 4 mod 32 -> 8 rows x 4 cols hit
// all 32 banks, conflict-free fragment loads. 4 arrays * 128*20*4B = 40KB.
__global__ __launch_bounds__(256)
void gemm_3xtf32(const float* __restrict__ A, const float* __restrict__ W,
                 const float* __restrict__ bias, float* __restrict__ C,
                 int M, int N, int K) {
    __shared__ float AsH[128][20], AsL[128][20];
    __shared__ float BsH[128][20], BsL[128][20];
    int tid = threadIdx.x;
    int bm = blockIdx.y * 128, bn = blockIdx.x * 128;
    int wid = tid >> 5, lane = tid & 31;
    int wm = (wid & 3) * 32, wn = (wid >> 2) * 64;
    int group = lane >> 2, tg = lane & 3;

    float c[2][8][4];
#pragma unroll
    for (int mt = 0; mt < 2; mt++)
#pragma unroll
        for (int nt = 0; nt < 8; nt++)
#pragma unroll
            for (int i = 0; i < 4; i++) c[mt][nt][i] = 0.f;

    for (int kk = 0; kk < K; kk += 16) {
        // global -> smem with hi/lo tf32 split
#pragma unroll
        for (int i = 0; i < 2; i++) {
            int lin = tid + i * 256;            // 0..511
            int r = lin >> 2, c4 = (lin & 3) * 4;
            float4 av = *(const float4*)&A[(size_t)(bm + r) * K + kk + c4];
            float4 wv = *(const float4*)&W[(size_t)(bn + r) * K + kk + c4];
            uint4 ah, al, bh, bl;
#define SPLIT(srcv, hv, lv)                                              \
            { unsigned h_;                                               \
              asm("cvt.rna.tf32.f32 %0, %1;" : "=r"(h_) : "f"(srcv));    \
              float r_ = (srcv) - __uint_as_float(h_);                   \
              unsigned l_;                                               \
              asm("cvt.rna.tf32.f32 %0, %1;" : "=r"(l_) : "f"(r_));      \
              hv = h_; lv = l_; }
            SPLIT(av.x, ah.x, al.x) SPLIT(av.y, ah.y, al.y)
            SPLIT(av.z, ah.z, al.z) SPLIT(av.w, ah.w, al.w)
            SPLIT(wv.x, bh.x, bl.x) SPLIT(wv.y, bh.y, bl.y)
            SPLIT(wv.z, bh.z, bl.z) SPLIT(wv.w, bh.w, bl.w)
#undef SPLIT
            *(uint4*)&AsH[r][c4] = ah;  *(uint4*)&AsL[r][c4] = al;
            *(uint4*)&BsH[r][c4] = bh;  *(uint4*)&BsL[r][c4] = bl;
        }
        __syncthreads();

#pragma unroll
        for (int ks = 0; ks < 2; ks++) {
            int k = ks * 8;
            unsigned aH[2][4], aL[2][4], bH[8][2], bL[8][2];
#pragma unroll
            for (int mt = 0; mt < 2; mt++) {
                int row = wm + mt * 16 + group;
                aH[mt][0] = __float_as_uint(AsH[row][k + tg]);
                aH[mt][1] = __float_as_uint(AsH[row + 8][k + tg]);
                aH[mt][2] = __float_as_uint(AsH[row][k + tg + 4]);
                aH[mt][3] = __float_as_uint(AsH[row + 8][k + tg + 4]);
                aL[mt][0] = __float_as_uint(AsL[row][k + tg]);
                aL[mt][1] = __float_as_uint(AsL[row + 8][k + tg]);
                aL[mt][2] = __float_as_uint(AsL[row][k + tg + 4]);
                aL[mt][3] = __float_as_uint(AsL[row + 8][k + tg + 4]);
            }
#pragma unroll
            for (int nt = 0; nt < 8; nt++) {
                int col = wn + nt * 8 + group;
                bH[nt][0] = __float_as_uint(BsH[col][k + tg]);
                bH[nt][1] = __float_as_uint(BsH[col][k + tg + 4]);
                bL[nt][0] = __float_as_uint(BsL[col][k + tg]);
                bL[nt][1] = __float_as_uint(BsL[col][k + tg + 4]);
            }
#define MMA(cc, aa, bb)                                                       \
            asm volatile(                                                     \
                "mma.sync.aligned.m16n8k8.row.col.f32.tf32.tf32.f32 "         \
                "{%0,%1,%2,%3}, {%4,%5,%6,%7}, {%8,%9}, {%0,%1,%2,%3};"       \
                : "+f"(cc[0]), "+f"(cc[1]), "+f"(cc[2]), "+f"(cc[3])          \
                : "r"(aa[0]), "r"(aa[1]), "r"(aa[2]), "r"(aa[3]),             \
                  "r"(bb[0]), "r"(bb[1]))
#pragma unroll
            for (int mt = 0; mt < 2; mt++)
#pragma unroll
                for (int nt = 0; nt < 8; nt++) {
                    MMA(c[mt][nt], aH[mt], bL[nt]);
                    MMA(c[mt][nt], aL[mt], bH[nt]);
                    MMA(c[mt][nt], aH[mt], bH[nt]);
                }
#undef MMA
        }
        __syncthreads();
    }

    // epilogue: add bias, write fp32
#pragma unroll
    for (int mt = 0; mt < 2; mt++) {
        int row0 = bm + wm + mt * 16 + group;
#pragma unroll
        for (int nt = 0; nt < 8; nt++) {
            int col = bn + wn + nt * 8 + tg * 2;
            float b0 = bias[col], b1 = bias[col + 1];
            *(float2*)&C[(size_t)row0 * N + col] =
                make_float2(c[mt][nt][0] + b0, c[mt][nt][1] + b1);
            *(float2*)&C[(size_t)(row0 + 8) * N + col] =
                make_float2(c[mt][nt][2] + b0, c[mt][nt][3] + b1);
        }
    }
}

// ---------------- per-(b,h,l) squared L2 norm of q -----------------------------
__global__ void qnorm_kernel(const float* __restrict__ Q, float* __restrict__ norms) {
    int gw = blockIdx.x * 8 + (threadIdx.x >> 5);
    int lane = threadIdx.x & 31;
    if (gw >= BHn * Lsz) return;
    int l = gw % Lsz;
    int h = (gw / Lsz) % Hn;
    int b = gw / (Lsz * Hn);
    const float* row = Q + (size_t)(b * Lsz + l) * Dsz + h * HDs;
    float v0 = row[lane], v1 = row[lane + 32];
    float ss = v0*v0 + v1*v1;
#pragma unroll
    for (int o = 16; o; o >>= 1) ss += __shfl_xor_sync(0xffffffffu, ss, o);
    if (lane == 0) norms[(b * Hn + h) * Lsz + l] = ss;
}

// ---------------- exact top-k per (b,h): bitonic sort + tie handling -----------
__global__ void topk_kernel(const float* __restrict__ norms, int* __restrict__ sel) {
    int bh = blockIdx.x;
    __shared__ float s[Lsz];
    __shared__ int cnt_out;
    __shared__ int cnt_gt;
    const float* nb = norms + (size_t)bh * Lsz;
    int tid = threadIdx.x;
    for (int i = tid; i < Lsz; i += 256) s[i] = nb[i];
    __syncthreads();
    for (int ksz = 2; ksz <= Lsz; ksz <<= 1) {
        for (int j = ksz >> 1; j > 0; j >>= 1) {
            for (int idx = tid; idx < Lsz; idx += 256) {
                int ixj = idx ^ j;
                if (ixj > idx) {
                    bool desc = ((idx & ksz) == 0);
                    float a = s[idx], bb = s[ixj];
                    bool sw = desc ? (a < bb) : (a > bb);
                    if (sw) { s[idx] = bb; s[ixj] = a; }
                }
            }
            __syncthreads();
        }
    }
    float t = s[KTOPn - 1];
    if (tid == 0) { cnt_out = 0; cnt_gt = 0; }
    __syncthreads();
    int lc = 0;
    for (int i = tid; i < Lsz; i += 256) lc += (nb[i] > t) ? 1 : 0;
    atomicAdd(&cnt_gt, lc);
    __syncthreads();
    int need = KTOPn - cnt_gt;
    for (int i = tid; i < Lsz; i += 256) {
        float v = nb[i];
        bool pick = false;
        if (v > t) pick = true;
        else if (v == t) {
            int eqb = 0;
            for (int jj = 0; jj < i; jj++) eqb += (nb[jj] == t) ? 1 : 0;
            pick = (eqb < need);
        }
        if (pick) {
            int p = atomicAdd(&cnt_out, 1);
            sel[(size_t)bh * KTOPn + p] = i;
        }
    }
}

// ---------------- V column means: partial sums then reduce ---------------------
__global__ void vpartial_kernel(const float* __restrict__ V, float* __restrict__ part) {
    int b = blockIdx.x >> 5, c = blockIdx.x & 31;
    int d = threadIdx.x;
    float sum = 0.f;
#pragma unroll 4
    for (int r = 0; r < 64; r++)
        sum += V[(size_t)(b * Lsz + c * 64 + r) * Dsz + d];
    part[(size_t)(b * 32 + c) * Dsz + d] = sum;
}

__global__ void vmean_kernel(const float* __restrict__ part, float* __restrict__ vm) {
    int i = blockIdx.x * 256 + threadIdx.x;
    if (i >= Bsz * Dsz) return;
    int b = i / Dsz, d = i % Dsz;
    float sum = 0.f;
#pragma unroll
    for (int c = 0; c < 32; c++) sum += part[(size_t)(b * 32 + c) * Dsz + d];
    vm[i] = sum * (1.0f / Lsz);
}

__global__ void fill_kernel(const float* __restrict__ vm, float* __restrict__ attn) {
    size_t i = (size_t)blockIdx.x * 256 + threadIdx.x;
    if (i >= (size_t)Bsz * Lsz * Dsz) return;
    int d = (int)(i % Dsz);
    int b = (int)(i / ((size_t)Lsz * Dsz));
    attn[i] = vm[b * Dsz + d];
}

// ---------------- flash attention over selected queries only -------------------
__global__ __launch_bounds__(256)
void attn_kernel(const float* __restrict__ Q, const float* __restrict__ K,
                 const float* __restrict__ V, const int* __restrict__ sel,
                 float* __restrict__ out) {
    __shared__ float Qs[32][64];
    __shared__ float buf[64][68];
    __shared__ float Ps[32][64];
    __shared__ int   sidx[32];

    int bh = blockIdx.y;
    int b = bh / Hn, h = bh % Hn;
    int qbase = blockIdx.x * 32;
    int tid = threadIdx.x;
    int tx = tid & 15, ty = tid >> 4;

    if (tid < 32) {
        int qi = qbase + tid;
        sidx[tid] = (qi < KTOPn) ? sel[(size_t)bh * KTOPn + qi] : -1;
    }
    __syncthreads();
    for (int i = tid; i < 32 * 16; i += 256) {
        int r = i >> 4, c4 = (i & 15) * 4;
        float4 v = make_float4(0.f, 0.f, 0.f, 0.f);
        int sl = sidx[r];
        if (sl >= 0)
            v = *(const float4*)&Q[(size_t)(b * Lsz + sl) * Dsz + h * HDs + c4];
        *(float4*)&Qs[r][c4] = v;
    }

    float m_i[2] = { -INFINITY, -INFINITY };
    float l_i[2] = { 0.f, 0.f };
    float acc[2][4] = { {0.f,0.f,0.f,0.f}, {0.f,0.f,0.f,0.f} };

    for (int kt = 0; kt < Lsz; kt += 64) {
        __syncthreads();
        for (int i = tid; i < 64 * 16; i += 256) {
            int r = i >> 4, c4 = (i & 15) * 4;
            float4 kv = *(const float4*)&K[(size_t)(b * Lsz + kt + r) * Dsz + h * HDs + c4];
            buf[c4+0][r] = kv.x; buf[c4+1][r] = kv.y; buf[c4+2][r] = kv.z; buf[c4+3][r] = kv.w;
        }
        __syncthreads();

        float s[2][4] = { {0,0,0,0}, {0,0,0,0} };
#pragma unroll
        for (int dq = 0; dq < 16; dq++) {
            float4 q0 = *(float4*)&Qs[ty*2+0][dq*4];
            float4 q1 = *(float4*)&Qs[ty*2+1][dq*4];
#pragma unroll
            for (int dd = 0; dd < 4; dd++) {
                float4 kv = *(float4*)&buf[dq*4+dd][tx*4];
                float qa = (&q0.x)[dd], qb = (&q1.x)[dd];
                s[0][0] += qa*kv.x; s[0][1] += qa*kv.y; s[0][2] += qa*kv.z; s[0][3] += qa*kv.w;
                s[1][0] += qb*kv.x; s[1][1] += qb*kv.y; s[1][2] += qb*kv.z; s[1][3] += qb*kv.w;
            }
        }

        float corr[2];
#pragma unroll
        for (int i = 0; i < 2; i++) {
#pragma unroll
            for (int j = 0; j < 4; j++) s[i][j] *= SCALE;
            float m = fmaxf(fmaxf(s[i][0], s[i][1]), fmaxf(s[i][2], s[i][3]));
            m = fmaxf(m, __shfl_xor_sync(0xffffffffu, m, 1, 16));
            m = fmaxf(m, __shfl_xor_sync(0xffffffffu, m, 2, 16));
            m = fmaxf(m, __shfl_xor_sync(0xffffffffu, m, 4, 16));
            m = fmaxf(m, __shfl_xor_sync(0xffffffffu, m, 8, 16));
            float mnew = fmaxf(m_i[i], m);
            float p[4], ps = 0.f;
#pragma unroll
            for (int j = 0; j < 4; j++) {
                p[j] = __expf(s[i][j] - mnew);
                Ps[ty*2+i][tx*4+j] = p[j];
                ps += p[j];
            }
            ps += __shfl_xor_sync(0xffffffffu, ps, 1, 16);
            ps += __shfl_xor_sync(0xffffffffu, ps, 2, 16);
            ps += __shfl_xor_sync(0xffffffffu, ps, 4, 16);
            ps += __shfl_xor_sync(0xffffffffu, ps, 8, 16);
            corr[i] = __expf(m_i[i] - mnew);
            l_i[i] = l_i[i] * corr[i] + ps;
            m_i[i] = mnew;
        }

        __syncthreads();
        for (int i = tid; i < 64 * 16; i += 256) {
            int r = i >> 4, c4 = (i & 15) * 4;
            float4 vv = *(const float4*)&V[(size_t)(b * Lsz + kt + r) * Dsz + h * HDs + c4];
            *(float4*)&buf[r][c4] = vv;
        }
        __syncthreads();

#pragma unroll
        for (int i = 0; i < 2; i++)
#pragma unroll
            for (int j = 0; j < 4; j++) acc[i][j] *= corr[i];

#pragma unroll
        for (int kq = 0; kq < 16; kq++) {
            float4 p0 = *(float4*)&Ps[ty*2+0][kq*4];
            float4 p1 = *(float4*)&Ps[ty*2+1][kq*4];
#pragma unroll
            for (int dd = 0; dd < 4; dd++) {
                float4 vv = *(float4*)&buf[kq*4+dd][tx*4];
                float pa = (&p0.x)[dd], pb = (&p1.x)[dd];
                acc[0][0] += pa*vv.x; acc[0][1] += pa*vv.y; acc[0][2] += pa*vv.z; acc[0][3] += pa*vv.w;
                acc[1][0] += pb*vv.x; acc[1][1] += pb*vv.y; acc[1][2] += pb*vv.z; acc[1][3] += pb*vv.w;
            }
        }
    }

#pragma unroll
    for (int i = 0; i < 2; i++) {
        int q = ty*2 + i;
        if (qbase + q < KTOPn) {
            int sl = sidx[q];
            float inv = 1.0f / l_i[i];
            float4 o = make_float4(acc[i][0]*inv, acc[i][1]*inv, acc[i][2]*inv, acc[i][3]*inv);
            *(float4*)&out[(size_t)(b * Lsz + sl) * Dsz + h * HDs + tx*4] = o;
        }
    }
}

// ---------------- launch -------------------------------------------------------
extern "C" void kernel_launch(void* const* d_in, const int* in_sizes, int n_in,
                              void* d_out, int out_size) {
    const float* x  = (const float*)d_in[0];
    const float* Wq = (const float*)d_in[1];
    const float* bq = (const float*)d_in[2];
    const float* Wk = (const float*)d_in[3];
    const float* bk = (const float*)d_in[4];
    const float* Wv = (const float*)d_in[5];
    const float* bv = (const float*)d_in[6];
    const float* Wo = (const float*)d_in[7];
    const float* bo = (const float*)d_in[8];
    float* out = (float*)d_out;

    float *pQ, *pK, *pV, *pA, *pN, *pPart, *pM;
    int* pS;
    cudaGetSymbolAddress((void**)&pQ, g_Q);
    cudaGetSymbolAddress((void**)&pK, g_K);
    cudaGetSymbolAddress((void**)&pV, g_V);
    cudaGetSymbolAddress((void**)&pA, g_A);
    cudaGetSymbolAddress((void**)&pN, g_norm);
    cudaGetSymbolAddress((void**)&pS, g_sel);
    cudaGetSymbolAddress((void**)&pPart, g_part);
    cudaGetSymbolAddress((void**)&pM, g_vmean);

    const int M = Bsz * Lsz;   // 4096
    dim3 gemm_grid(Dsz / 128, M / 128);

    gemm_3xtf32<<<gemm_grid, 256>>>(x, Wq, bq, pQ, M, Dsz, Dsz);
    gemm_3xtf32<<<gemm_grid, 256>>>(x, Wk, bk, pK, M, Dsz, Dsz);
    gemm_3xtf32<<<gemm_grid, 256>>>(x, Wv, bv, pV, M, Dsz, Dsz);

    qnorm_kernel<<<(BHn * Lsz) / 8, 256>>>(pQ, pN);
    topk_kernel<<<BHn, 256>>>(pN, pS);

    vpartial_kernel<<<Bsz * 32, 1024>>>(pV, pPart);
    vmean_kernel<<<(Bsz * Dsz + 255) / 256, 256>>>(pPart, pM);
    fill_kernel<<<(Bsz * Lsz * Dsz) / 256, 256>>>(pM, pA);

    attn_kernel<<<dim3((KTOPn + 31) / 32, BHn), 256>>>(pQ, pK, pV, pS, pA);

    gemm_3xtf32<<<gemm_grid, 256>>>(pA, Wo, bo, out, M, Dsz, Dsz);
}

// round 5
// speedup vs baseline: 1.5844x; 1.3830x over previous
#include <cuda_runtime.h>
#include <math.h>

#define Bsz 2
#define Lsz 2048
#define Dsz 1024
#define Hn  16
#define HDs 64
#define KTOPn 409
#define BHn (Bsz*Hn)
#define SCALE 0.125f

// ---------------- scratch (device globals: allocation-free rule) ----------------
__device__ float g_Q[Bsz*Lsz*Dsz];
__device__ float g_K[Bsz*Lsz*Dsz];
__device__ float g_V[Bsz*Lsz*Dsz];
__device__ float g_A[Bsz*Lsz*Dsz];       // attention output, [B,L,H*HD]
__device__ float g_norm[BHn*Lsz];
__device__ int   g_sel[BHn*KTOPn];
__device__ float g_part[Bsz*32*Dsz];
__device__ float g_vmean[Bsz*Dsz];

#define CVT_TF32(dst, src) asm("cvt.rna.tf32.f32 %0, %1;" : "=r"(dst) : "f"(src))

#define MMA_TF32(cc, aa, bb)                                                  \
    asm volatile(                                                             \
        "mma.sync.aligned.m16n8k8.row.col.f32.tf32.tf32.f32 "                 \
        "{%0,%1,%2,%3}, {%4,%5,%6,%7}, {%8,%9}, {%0,%1,%2,%3};"               \
        : "+f"(cc[0]), "+f"(cc[1]), "+f"(cc[2]), "+f"(cc[3])                  \
        : "r"(aa[0]), "r"(aa[1]), "r"(aa[2]), "r"(aa[3]),                     \
          "r"(bb[0]), "r"(bb[1]))

// ------------- 3xTF32 tensor-core GEMM (Q projection: top-k needs fp32 grade) --
// 128x128 tile, BK=16, 256 threads (8 warps as 4x2), mma.sync.m16n8k8.tf32.
// hi=tf32(x), lo=tf32(x-hi); c += hi*hi + hi*lo + lo*hi. Error ~2^-22.
// Smem row pad 20: stride == 4 mod 32 -> conflict-free fragment loads.
__global__ __launch_bounds__(256)
void gemm_3xtf32(const float* __restrict__ A, const float* __restrict__ W,
                 const float* __restrict__ bias, float* __restrict__ C,
                 int M, int N, int K) {
    __shared__ float AsH[128][20], AsL[128][20];
    __shared__ float BsH[128][20], BsL[128][20];
    int tid = threadIdx.x;
    int bm = blockIdx.y * 128, bn = blockIdx.x * 128;
    int wid = tid >> 5, lane = tid & 31;
    int wm = (wid & 3) * 32, wn = (wid >> 2) * 64;
    int group = lane >> 2, tg = lane & 3;

    float c[2][8][4];
#pragma unroll
    for (int mt = 0; mt < 2; mt++)
#pragma unroll
        for (int nt = 0; nt < 8; nt++)
#pragma unroll
            for (int i = 0; i < 4; i++) c[mt][nt][i] = 0.f;

    for (int kk = 0; kk < K; kk += 16) {
#pragma unroll
        for (int i = 0; i < 2; i++) {
            int lin = tid + i * 256;
            int r = lin >> 2, c4 = (lin & 3) * 4;
            float4 av = *(const float4*)&A[(size_t)(bm + r) * K + kk + c4];
            float4 wv = *(const float4*)&W[(size_t)(bn + r) * K + kk + c4];
            uint4 ah, al, bh, bl;
#define SPLIT(srcv, hv, lv)                                              \
            { unsigned h_; CVT_TF32(h_, srcv);                           \
              float r_ = (srcv) - __uint_as_float(h_);                   \
              unsigned l_; CVT_TF32(l_, r_);                             \
              hv = h_; lv = l_; }
            SPLIT(av.x, ah.x, al.x) SPLIT(av.y, ah.y, al.y)
            SPLIT(av.z, ah.z, al.z) SPLIT(av.w, ah.w, al.w)
            SPLIT(wv.x, bh.x, bl.x) SPLIT(wv.y, bh.y, bl.y)
            SPLIT(wv.z, bh.z, bl.z) SPLIT(wv.w, bh.w, bl.w)
#undef SPLIT
            *(uint4*)&AsH[r][c4] = ah;  *(uint4*)&AsL[r][c4] = al;
            *(uint4*)&BsH[r][c4] = bh;  *(uint4*)&BsL[r][c4] = bl;
        }
        __syncthreads();

#pragma unroll
        for (int ks = 0; ks < 2; ks++) {
            int k = ks * 8;
            unsigned aH[2][4], aL[2][4], bH[8][2], bL[8][2];
#pragma unroll
            for (int mt = 0; mt < 2; mt++) {
                int row = wm + mt * 16 + group;
                aH[mt][0] = __float_as_uint(AsH[row][k + tg]);
                aH[mt][1] = __float_as_uint(AsH[row + 8][k + tg]);
                aH[mt][2] = __float_as_uint(AsH[row][k + tg + 4]);
                aH[mt][3] = __float_as_uint(AsH[row + 8][k + tg + 4]);
                aL[mt][0] = __float_as_uint(AsL[row][k + tg]);
                aL[mt][1] = __float_as_uint(AsL[row + 8][k + tg]);
                aL[mt][2] = __float_as_uint(AsL[row][k + tg + 4]);
                aL[mt][3] = __float_as_uint(AsL[row + 8][k + tg + 4]);
            }
#pragma unroll
            for (int nt = 0; nt < 8; nt++) {
                int col = wn + nt * 8 + group;
                bH[nt][0] = __float_as_uint(BsH[col][k + tg]);
                bH[nt][1] = __float_as_uint(BsH[col][k + tg + 4]);
                bL[nt][0] = __float_as_uint(BsL[col][k + tg]);
                bL[nt][1] = __float_as_uint(BsL[col][k + tg + 4]);
            }
#pragma unroll
            for (int mt = 0; mt < 2; mt++)
#pragma unroll
                for (int nt = 0; nt < 8; nt++) {
                    MMA_TF32(c[mt][nt], aH[mt], bL[nt]);
                    MMA_TF32(c[mt][nt], aL[mt], bH[nt]);
                    MMA_TF32(c[mt][nt], aH[mt], bH[nt]);
                }
        }
        __syncthreads();
    }

#pragma unroll
    for (int mt = 0; mt < 2; mt++) {
        int row0 = bm + wm + mt * 16 + group;
#pragma unroll
        for (int nt = 0; nt < 8; nt++) {
            int col = bn + wn + nt * 8 + tg * 2;
            float b0 = bias[col], b1 = bias[col + 1];
            *(float2*)&C[(size_t)row0 * N + col] =
                make_float2(c[mt][nt][0] + b0, c[mt][nt][1] + b1);
            *(float2*)&C[(size_t)(row0 + 8) * N + col] =
                make_float2(c[mt][nt][2] + b0, c[mt][nt][3] + b1);
        }
    }
}

// ------------- 1xTF32 tensor-core GEMM (K/V/O: smooth consumers, ~1.4e-4 ok) ---
// 128x128 tile, BK=32, 256 threads, single mma per fragment pair (1/3 the MMAs).
// Smem row pad 36: stride == 4 mod 32 -> conflict-free fragment loads.
__global__ __launch_bounds__(256)
void gemm_1xtf32(const float* __restrict__ A, const float* __restrict__ W,
                 const float* __restrict__ bias, float* __restrict__ C,
                 int M, int N, int K) {
    __shared__ float As[128][36];
    __shared__ float Bs[128][36];
    int tid = threadIdx.x;
    int bm = blockIdx.y * 128, bn = blockIdx.x * 128;
    int wid = tid >> 5, lane = tid & 31;
    int wm = (wid & 3) * 32, wn = (wid >> 2) * 64;
    int group = lane >> 2, tg = lane & 3;

    float c[2][8][4];
#pragma unroll
    for (int mt = 0; mt < 2; mt++)
#pragma unroll
        for (int nt = 0; nt < 8; nt++)
#pragma unroll
            for (int i = 0; i < 4; i++) c[mt][nt][i] = 0.f;

    for (int kk = 0; kk < K; kk += 32) {
#pragma unroll
        for (int i = 0; i < 4; i++) {
            int lin = tid + i * 256;            // 0..1023
            int r = lin >> 3, c4 = (lin & 7) * 4;
            float4 av = *(const float4*)&A[(size_t)(bm + r) * K + kk + c4];
            float4 wv = *(const float4*)&W[(size_t)(bn + r) * K + kk + c4];
            uint4 at, bt;
            CVT_TF32(at.x, av.x); CVT_TF32(at.y, av.y);
            CVT_TF32(at.z, av.z); CVT_TF32(at.w, av.w);
            CVT_TF32(bt.x, wv.x); CVT_TF32(bt.y, wv.y);
            CVT_TF32(bt.z, wv.z); CVT_TF32(bt.w, wv.w);
            *(uint4*)&As[r][c4] = at;
            *(uint4*)&Bs[r][c4] = bt;
        }
        __syncthreads();

#pragma unroll
        for (int ks = 0; ks < 4; ks++) {
            int k = ks * 8;
            unsigned a[2][4], b[8][2];
#pragma unroll
            for (int mt = 0; mt < 2; mt++) {
                int row = wm + mt * 16 + group;
                a[mt][0] = __float_as_uint(As[row][k + tg]);
                a[mt][1] = __float_as_uint(As[row + 8][k + tg]);
                a[mt][2] = __float_as_uint(As[row][k + tg + 4]);
                a[mt][3] = __float_as_uint(As[row + 8][k + tg + 4]);
            }
#pragma unroll
            for (int nt = 0; nt < 8; nt++) {
                int col = wn + nt * 8 + group;
                b[nt][0] = __float_as_uint(Bs[col][k + tg]);
                b[nt][1] = __float_as_uint(Bs[col][k + tg + 4]);
            }
#pragma unroll
            for (int mt = 0; mt < 2; mt++)
#pragma unroll
                for (int nt = 0; nt < 8; nt++)
                    MMA_TF32(c[mt][nt], a[mt], b[nt]);
        }
        __syncthreads();
    }

#pragma unroll
    for (int mt = 0; mt < 2; mt++) {
        int row0 = bm + wm + mt * 16 + group;
#pragma unroll
        for (int nt = 0; nt < 8; nt++) {
            int col = bn + wn + nt * 8 + tg * 2;
            float b0 = bias[col], b1 = bias[col + 1];
            *(float2*)&C[(size_t)row0 * N + col] =
                make_float2(c[mt][nt][0] + b0, c[mt][nt][1] + b1);
            *(float2*)&C[(size_t)(row0 + 8) * N + col] =
                make_float2(c[mt][nt][2] + b0, c[mt][nt][3] + b1);
        }
    }
}

// ---------------- per-(b,h,l) squared L2 norm of q -----------------------------
__global__ void qnorm_kernel(const float* __restrict__ Q, float* __restrict__ norms) {
    int gw = blockIdx.x * 8 + (threadIdx.x >> 5);
    int lane = threadIdx.x & 31;
    if (gw >= BHn * Lsz) return;
    int l = gw % Lsz;
    int h = (gw / Lsz) % Hn;
    int b = gw / (Lsz * Hn);
    const float* row = Q + (size_t)(b * Lsz + l) * Dsz + h * HDs;
    float v0 = row[lane], v1 = row[lane + 32];
    float ss = v0*v0 + v1*v1;
#pragma unroll
    for (int o = 16; o; o >>= 1) ss += __shfl_xor_sync(0xffffffffu, ss, o);
    if (lane == 0) norms[(b * Hn + h) * Lsz + l] = ss;
}

// ---------------- exact top-k per (b,h): bitonic sort + tie handling -----------
__global__ void topk_kernel(const float* __restrict__ norms, int* __restrict__ sel) {
    int bh = blockIdx.x;
    __shared__ float s[Lsz];
    __shared__ int cnt_out;
    __shared__ int cnt_gt;
    const float* nb = norms + (size_t)bh * Lsz;
    int tid = threadIdx.x;
    for (int i = tid; i < Lsz; i += 256) s[i] = nb[i];
    __syncthreads();
    for (int ksz = 2; ksz <= Lsz; ksz <<= 1) {
        for (int j = ksz >> 1; j > 0; j >>= 1) {
            for (int idx = tid; idx < Lsz; idx += 256) {
                int ixj = idx ^ j;
                if (ixj > idx) {
                    bool desc = ((idx & ksz) == 0);
                    float a = s[idx], bb = s[ixj];
                    bool sw = desc ? (a < bb) : (a > bb);
                    if (sw) { s[idx] = bb; s[ixj] = a; }
                }
            }
            __syncthreads();
        }
    }
    float t = s[KTOPn - 1];
    if (tid == 0) { cnt_out = 0; cnt_gt = 0; }
    __syncthreads();
    int lc = 0;
    for (int i = tid; i < Lsz; i += 256) lc += (nb[i] > t) ? 1 : 0;
    atomicAdd(&cnt_gt, lc);
    __syncthreads();
    int need = KTOPn - cnt_gt;
    for (int i = tid; i < Lsz; i += 256) {
        float v = nb[i];
        bool pick = false;
        if (v > t) pick = true;
        else if (v == t) {
            int eqb = 0;
            for (int jj = 0; jj < i; jj++) eqb += (nb[jj] == t) ? 1 : 0;
            pick = (eqb < need);
        }
        if (pick) {
            int p = atomicAdd(&cnt_out, 1);
            sel[(size_t)bh * KTOPn + p] = i;
        }
    }
}

// ---------------- V column means -----------------------------------------------
__global__ void vpartial_kernel(const float* __restrict__ V, float* __restrict__ part) {
    int b = blockIdx.x >> 5, c = blockIdx.x & 31;
    int d = threadIdx.x;
    float sum = 0.f;
#pragma unroll 4
    for (int r = 0; r < 64; r++)
        sum += V[(size_t)(b * Lsz + c * 64 + r) * Dsz + d];
    part[(size_t)(b * 32 + c) * Dsz + d] = sum;
}

__global__ void vmean_kernel(const float* __restrict__ part, float* __restrict__ vm) {
    int i = blockIdx.x * 256 + threadIdx.x;
    if (i >= Bsz * Dsz) return;
    int b = i / Dsz, d = i % Dsz;
    float sum = 0.f;
#pragma unroll
    for (int c = 0; c < 32; c++) sum += part[(size_t)(b * 32 + c) * Dsz + d];
    vm[i] = sum * (1.0f / Lsz);
}

__global__ void fill_kernel(const float* __restrict__ vm, float* __restrict__ attn) {
    size_t i = (size_t)blockIdx.x * 256 + threadIdx.x;
    if (i >= (size_t)Bsz * Lsz * Dsz) return;
    int d = (int)(i % Dsz);
    int b = (int)(i / ((size_t)Lsz * Dsz));
    attn[i] = vm[b * Dsz + d];
}

// ---------------- flash attention over selected queries only -------------------
__global__ __launch_bounds__(256)
void attn_kernel(const float* __restrict__ Q, const float* __restrict__ K,
                 const float* __restrict__ V, const int* __restrict__ sel,
                 float* __restrict__ out) {
    __shared__ float Qs[32][64];
    __shared__ float buf[64][68];
    __shared__ float Ps[32][64];
    __shared__ int   sidx[32];

    int bh = blockIdx.y;
    int b = bh / Hn, h = bh % Hn;
    int qbase = blockIdx.x * 32;
    int tid = threadIdx.x;
    int tx = tid & 15, ty = tid >> 4;

    if (tid < 32) {
        int qi = qbase + tid;
        sidx[tid] = (qi < KTOPn) ? sel[(size_t)bh * KTOPn + qi] : -1;
    }
    __syncthreads();
    for (int i = tid; i < 32 * 16; i += 256) {
        int r = i >> 4, c4 = (i & 15) * 4;
        float4 v = make_float4(0.f, 0.f, 0.f, 0.f);
        int sl = sidx[r];
        if (sl >= 0)
            v = *(const float4*)&Q[(size_t)(b * Lsz + sl) * Dsz + h * HDs + c4];
        *(float4*)&Qs[r][c4] = v;
    }

    float m_i[2] = { -INFINITY, -INFINITY };
    float l_i[2] = { 0.f, 0.f };
    float acc[2][4] = { {0.f,0.f,0.f,0.f}, {0.f,0.f,0.f,0.f} };

    for (int kt = 0; kt < Lsz; kt += 64) {
        __syncthreads();
        for (int i = tid; i < 64 * 16; i += 256) {
            int r = i >> 4, c4 = (i & 15) * 4;
            float4 kv = *(const float4*)&K[(size_t)(b * Lsz + kt + r) * Dsz + h * HDs + c4];
            buf[c4+0][r] = kv.x; buf[c4+1][r] = kv.y; buf[c4+2][r] = kv.z; buf[c4+3][r] = kv.w;
        }
        __syncthreads();

        float s[2][4] = { {0,0,0,0}, {0,0,0,0} };
#pragma unroll
        for (int dq = 0; dq < 16; dq++) {
            float4 q0 = *(float4*)&Qs[ty*2+0][dq*4];
            float4 q1 = *(float4*)&Qs[ty*2+1][dq*4];
#pragma unroll
            for (int dd = 0; dd < 4; dd++) {
                float4 kv = *(float4*)&buf[dq*4+dd][tx*4];
                float qa = (&q0.x)[dd], qb = (&q1.x)[dd];
                s[0][0] += qa*kv.x; s[0][1] += qa*kv.y; s[0][2] += qa*kv.z; s[0][3] += qa*kv.w;
                s[1][0] += qb*kv.x; s[1][1] += qb*kv.y; s[1][2] += qb*kv.z; s[1][3] += qb*kv.w;
            }
        }

        float corr[2];
#pragma unroll
        for (int i = 0; i < 2; i++) {
#pragma unroll
            for (int j = 0; j < 4; j++) s[i][j] *= SCALE;
            float m = fmaxf(fmaxf(s[i][0], s[i][1]), fmaxf(s[i][2], s[i][3]));
            m = fmaxf(m, __shfl_xor_sync(0xffffffffu, m, 1, 16));
            m = fmaxf(m, __shfl_xor_sync(0xffffffffu, m, 2, 16));
            m = fmaxf(m, __shfl_xor_sync(0xffffffffu, m, 4, 16));
            m = fmaxf(m, __shfl_xor_sync(0xffffffffu, m, 8, 16));
            float mnew = fmaxf(m_i[i], m);
            float p[4], ps = 0.f;
#pragma unroll
            for (int j = 0; j < 4; j++) {
                p[j] = __expf(s[i][j] - mnew);
                Ps[ty*2+i][tx*4+j] = p[j];
                ps += p[j];
            }
            ps += __shfl_xor_sync(0xffffffffu, ps, 1, 16);
            ps += __shfl_xor_sync(0xffffffffu, ps, 2, 16);
            ps += __shfl_xor_sync(0xffffffffu, ps, 4, 16);
            ps += __shfl_xor_sync(0xffffffffu, ps, 8, 16);
            corr[i] = __expf(m_i[i] - mnew);
            l_i[i] = l_i[i] * corr[i] + ps;
            m_i[i] = mnew;
        }

        __syncthreads();
        for (int i = tid; i < 64 * 16; i += 256) {
            int r = i >> 4, c4 = (i & 15) * 4;
            float4 vv = *(const float4*)&V[(size_t)(b * Lsz + kt + r) * Dsz + h * HDs + c4];
            *(float4*)&buf[r][c4] = vv;
        }
        __syncthreads();

#pragma unroll
        for (int i = 0; i < 2; i++)
#pragma unroll
            for (int j = 0; j < 4; j++) acc[i][j] *= corr[i];

#pragma unroll
        for (int kq = 0; kq < 16; kq++) {
            float4 p0 = *(float4*)&Ps[ty*2+0][kq*4];
            float4 p1 = *(float4*)&Ps[ty*2+1][kq*4];
#pragma unroll
            for (int dd = 0; dd < 4; dd++) {
                float4 vv = *(float4*)&buf[kq*4+dd][tx*4];
                float pa = (&p0.x)[dd], pb = (&p1.x)[dd];
                acc[0][0] += pa*vv.x; acc[0][1] += pa*vv.y; acc[0][2] += pa*vv.z; acc[0][3] += pa*vv.w;
                acc[1][0] += pb*vv.x; acc[1][1] += pb*vv.y; acc[1][2] += pb*vv.z; acc[1][3] += pb*vv.w;
            }
        }
    }

#pragma unroll
    for (int i = 0; i < 2; i++) {
        int q = ty*2 + i;
        if (qbase + q < KTOPn) {
            int sl = sidx[q];
            float inv = 1.0f / l_i[i];
            float4 o = make_float4(acc[i][0]*inv, acc[i][1]*inv, acc[i][2]*inv, acc[i][3]*inv);
            *(float4*)&out[(size_t)(b * Lsz + sl) * Dsz + h * HDs + tx*4] = o;
        }
    }
}

// ---------------- launch -------------------------------------------------------
extern "C" void kernel_launch(void* const* d_in, const int* in_sizes, int n_in,
                              void* d_out, int out_size) {
    const float* x  = (const float*)d_in[0];
    const float* Wq = (const float*)d_in[1];
    const float* bq = (const float*)d_in[2];
    const float* Wk = (const float*)d_in[3];
    const float* bk = (const float*)d_in[4];
    const float* Wv = (const float*)d_in[5];
    const float* bv = (const float*)d_in[6];
    const float* Wo = (const float*)d_in[7];
    const float* bo = (const float*)d_in[8];
    float* out = (float*)d_out;

    float *pQ, *pK, *pV, *pA, *pN, *pPart, *pM;
    int* pS;
    cudaGetSymbolAddress((void**)&pQ, g_Q);
    cudaGetSymbolAddress((void**)&pK, g_K);
    cudaGetSymbolAddress((void**)&pV, g_V);
    cudaGetSymbolAddress((void**)&pA, g_A);
    cudaGetSymbolAddress((void**)&pN, g_norm);
    cudaGetSymbolAddress((void**)&pS, g_sel);
    cudaGetSymbolAddress((void**)&pPart, g_part);
    cudaGetSymbolAddress((void**)&pM, g_vmean);

    const int M = Bsz * Lsz;   // 4096
    dim3 gemm_grid(Dsz / 128, M / 128);

    // Q needs near-fp32 precision (top-k selection is discontinuous); K/V/O are
    // smooth consumers and tolerate single-pass tf32 (~1.4e-4).
    gemm_3xtf32<<<gemm_grid, 256>>>(x, Wq, bq, pQ, M, Dsz, Dsz);
    gemm_1xtf32<<<gemm_grid, 256>>>(x, Wk, bk, pK, M, Dsz, Dsz);
    gemm_1xtf32<<<gemm_grid, 256>>>(x, Wv, bv, pV, M, Dsz, Dsz);

    qnorm_kernel<<<(BHn * Lsz) / 8, 256>>>(pQ, pN);
    topk_kernel<<<BHn, 256>>>(pN, pS);

    vpartial_kernel<<<Bsz * 32, 1024>>>(pV, pPart);
    vmean_kernel<<<(Bsz * Dsz + 255) / 256, 256>>>(pPart, pM);
    fill_kernel<<<(Bsz * Lsz * Dsz) / 256, 256>>>(pM, pA);

    attn_kernel<<<dim3((KTOPn + 31) / 32, BHn), 256>>>(pQ, pK, pV, pS, pA);

    gemm_1xtf32<<<gemm_grid, 256>>>(pA, Wo, bo, out, M, Dsz, Dsz);
}

// round 6
// speedup vs baseline: 2.2122x; 1.3962x over previous
#include <cuda_runtime.h>
#include <math.h>

#define Bsz 2
#define Lsz 2048
#define Dsz 1024
#define Hn  16
#define HDs 64
#define KTOPn 409
#define BHn (Bsz*Hn)
#define SCALE 0.125f

// ---------------- scratch (device globals: allocation-free rule) ----------------
__device__ float g_Q[Bsz*Lsz*Dsz];
__device__ float g_K[Bsz*Lsz*Dsz];
__device__ float g_V[Bsz*Lsz*Dsz];
__device__ float g_A[Bsz*Lsz*Dsz];       // attention output, [B,L,H*HD]
__device__ float g_norm[BHn*Lsz];
__device__ int   g_sel[BHn*KTOPn];
__device__ float g_part[Bsz*32*Dsz];
__device__ float g_vmean[Bsz*Dsz];

#define CVT_TF32(dst, src) asm("cvt.rna.tf32.f32 %0, %1;" : "=r"(dst) : "f"(src))

#define MMA_TF32(cc, aa, bb)                                                  \
    asm volatile(                                                             \
        "mma.sync.aligned.m16n8k8.row.col.f32.tf32.tf32.f32 "                 \
        "{%0,%1,%2,%3}, {%4,%5,%6,%7}, {%8,%9}, {%0,%1,%2,%3};"               \
        : "+f"(cc[0]), "+f"(cc[1]), "+f"(cc[2]), "+f"(cc[3])                  \
        : "r"(aa[0]), "r"(aa[1]), "r"(aa[2]), "r"(aa[3]),                     \
          "r"(bb[0]), "r"(bb[1]))

// ------------- 3xTF32 tensor-core GEMM (Q projection: top-k needs fp32 grade) --
__global__ __launch_bounds__(256)
void gemm_3xtf32(const float* __restrict__ A, const float* __restrict__ W,
                 const float* __restrict__ bias, float* __restrict__ C,
                 int M, int N, int K) {
    __shared__ float AsH[128][20], AsL[128][20];
    __shared__ float BsH[128][20], BsL[128][20];
    int tid = threadIdx.x;
    int bm = blockIdx.y * 128, bn = blockIdx.x * 128;
    int wid = tid >> 5, lane = tid & 31;
    int wm = (wid & 3) * 32, wn = (wid >> 2) * 64;
    int group = lane >> 2, tg = lane & 3;

    float c[2][8][4];
#pragma unroll
    for (int mt = 0; mt < 2; mt++)
#pragma unroll
        for (int nt = 0; nt < 8; nt++)
#pragma unroll
            for (int i = 0; i < 4; i++) c[mt][nt][i] = 0.f;

    for (int kk = 0; kk < K; kk += 16) {
#pragma unroll
        for (int i = 0; i < 2; i++) {
            int lin = tid + i * 256;
            int r = lin >> 2, c4 = (lin & 3) * 4;
            float4 av = *(const float4*)&A[(size_t)(bm + r) * K + kk + c4];
            float4 wv = *(const float4*)&W[(size_t)(bn + r) * K + kk + c4];
            uint4 ah, al, bh, bl;
#define SPLIT(srcv, hv, lv)                                              \
            { unsigned h_; CVT_TF32(h_, srcv);                           \
              float r_ = (srcv) - __uint_as_float(h_);                   \
              unsigned l_; CVT_TF32(l_, r_);                             \
              hv = h_; lv = l_; }
            SPLIT(av.x, ah.x, al.x) SPLIT(av.y, ah.y, al.y)
            SPLIT(av.z, ah.z, al.z) SPLIT(av.w, ah.w, al.w)
            SPLIT(wv.x, bh.x, bl.x) SPLIT(wv.y, bh.y, bl.y)
            SPLIT(wv.z, bh.z, bl.z) SPLIT(wv.w, bh.w, bl.w)
#undef SPLIT
            *(uint4*)&AsH[r][c4] = ah;  *(uint4*)&AsL[r][c4] = al;
            *(uint4*)&BsH[r][c4] = bh;  *(uint4*)&BsL[r][c4] = bl;
        }
        __syncthreads();

#pragma unroll
        for (int ks = 0; ks < 2; ks++) {
            int k = ks * 8;
            unsigned aH[2][4], aL[2][4], bH[8][2], bL[8][2];
#pragma unroll
            for (int mt = 0; mt < 2; mt++) {
                int row = wm + mt * 16 + group;
                aH[mt][0] = __float_as_uint(AsH[row][k + tg]);
                aH[mt][1] = __float_as_uint(AsH[row + 8][k + tg]);
                aH[mt][2] = __float_as_uint(AsH[row][k + tg + 4]);
                aH[mt][3] = __float_as_uint(AsH[row + 8][k + tg + 4]);
                aL[mt][0] = __float_as_uint(AsL[row][k + tg]);
                aL[mt][1] = __float_as_uint(AsL[row + 8][k + tg]);
                aL[mt][2] = __float_as_uint(AsL[row][k + tg + 4]);
                aL[mt][3] = __float_as_uint(AsL[row + 8][k + tg + 4]);
            }
#pragma unroll
            for (int nt = 0; nt < 8; nt++) {
                int col = wn + nt * 8 + group;
                bH[nt][0] = __float_as_uint(BsH[col][k + tg]);
                bH[nt][1] = __float_as_uint(BsH[col][k + tg + 4]);
                bL[nt][0] = __float_as_uint(BsL[col][k + tg]);
                bL[nt][1] = __float_as_uint(BsL[col][k + tg + 4]);
            }
#pragma unroll
            for (int mt = 0; mt < 2; mt++)
#pragma unroll
                for (int nt = 0; nt < 8; nt++) {
                    MMA_TF32(c[mt][nt], aH[mt], bL[nt]);
                    MMA_TF32(c[mt][nt], aL[mt], bH[nt]);
                    MMA_TF32(c[mt][nt], aH[mt], bH[nt]);
                }
        }
        __syncthreads();
    }

#pragma unroll
    for (int mt = 0; mt < 2; mt++) {
        int row0 = bm + wm + mt * 16 + group;
#pragma unroll
        for (int nt = 0; nt < 8; nt++) {
            int col = bn + wn + nt * 8 + tg * 2;
            float b0 = bias[col], b1 = bias[col + 1];
            *(float2*)&C[(size_t)row0 * N + col] =
                make_float2(c[mt][nt][0] + b0, c[mt][nt][1] + b1);
            *(float2*)&C[(size_t)(row0 + 8) * N + col] =
                make_float2(c[mt][nt][2] + b0, c[mt][nt][3] + b1);
        }
    }
}

// ------------- 1xTF32 tensor-core GEMM (K/V/O: smooth consumers) ---------------
__global__ __launch_bounds__(256)
void gemm_1xtf32(const float* __restrict__ A, const float* __restrict__ W,
                 const float* __restrict__ bias, float* __restrict__ C,
                 int M, int N, int K) {
    __shared__ float As[128][36];
    __shared__ float Bs[128][36];
    int tid = threadIdx.x;
    int bm = blockIdx.y * 128, bn = blockIdx.x * 128;
    int wid = tid >> 5, lane = tid & 31;
    int wm = (wid & 3) * 32, wn = (wid >> 2) * 64;
    int group = lane >> 2, tg = lane & 3;

    float c[2][8][4];
#pragma unroll
    for (int mt = 0; mt < 2; mt++)
#pragma unroll
        for (int nt = 0; nt < 8; nt++)
#pragma unroll
            for (int i = 0; i < 4; i++) c[mt][nt][i] = 0.f;

    for (int kk = 0; kk < K; kk += 32) {
#pragma unroll
        for (int i = 0; i < 4; i++) {
            int lin = tid + i * 256;
            int r = lin >> 3, c4 = (lin & 7) * 4;
            float4 av = *(const float4*)&A[(size_t)(bm + r) * K + kk + c4];
            float4 wv = *(const float4*)&W[(size_t)(bn + r) * K + kk + c4];
            uint4 at, bt;
            CVT_TF32(at.x, av.x); CVT_TF32(at.y, av.y);
            CVT_TF32(at.z, av.z); CVT_TF32(at.w, av.w);
            CVT_TF32(bt.x, wv.x); CVT_TF32(bt.y, wv.y);
            CVT_TF32(bt.z, wv.z); CVT_TF32(bt.w, wv.w);
            *(uint4*)&As[r][c4] = at;
            *(uint4*)&Bs[r][c4] = bt;
        }
        __syncthreads();

#pragma unroll
        for (int ks = 0; ks < 4; ks++) {
            int k = ks * 8;
            unsigned a[2][4], b[8][2];
#pragma unroll
            for (int mt = 0; mt < 2; mt++) {
                int row = wm + mt * 16 + group;
                a[mt][0] = __float_as_uint(As[row][k + tg]);
                a[mt][1] = __float_as_uint(As[row + 8][k + tg]);
                a[mt][2] = __float_as_uint(As[row][k + tg + 4]);
                a[mt][3] = __float_as_uint(As[row + 8][k + tg + 4]);
            }
#pragma unroll
            for (int nt = 0; nt < 8; nt++) {
                int col = wn + nt * 8 + group;
                b[nt][0] = __float_as_uint(Bs[col][k + tg]);
                b[nt][1] = __float_as_uint(Bs[col][k + tg + 4]);
            }
#pragma unroll
            for (int mt = 0; mt < 2; mt++)
#pragma unroll
                for (int nt = 0; nt < 8; nt++)
                    MMA_TF32(c[mt][nt], a[mt], b[nt]);
        }
        __syncthreads();
    }

#pragma unroll
    for (int mt = 0; mt < 2; mt++) {
        int row0 = bm + wm + mt * 16 + group;
#pragma unroll
        for (int nt = 0; nt < 8; nt++) {
            int col = bn + wn + nt * 8 + tg * 2;
            float b0 = bias[col], b1 = bias[col + 1];
            *(float2*)&C[(size_t)row0 * N + col] =
                make_float2(c[mt][nt][0] + b0, c[mt][nt][1] + b1);
            *(float2*)&C[(size_t)(row0 + 8) * N + col] =
                make_float2(c[mt][nt][2] + b0, c[mt][nt][3] + b1);
        }
    }
}

// ---------------- per-(b,h,l) squared L2 norm of q -----------------------------
__global__ void qnorm_kernel(const float* __restrict__ Q, float* __restrict__ norms) {
    int gw = blockIdx.x * 8 + (threadIdx.x >> 5);
    int lane = threadIdx.x & 31;
    if (gw >= BHn * Lsz) return;
    int l = gw % Lsz;
    int h = (gw / Lsz) % Hn;
    int b = gw / (Lsz * Hn);
    const float* row = Q + (size_t)(b * Lsz + l) * Dsz + h * HDs;
    float v0 = row[lane], v1 = row[lane + 32];
    float ss = v0*v0 + v1*v1;
#pragma unroll
    for (int o = 16; o; o >>= 1) ss += __shfl_xor_sync(0xffffffffu, ss, o);
    if (lane == 0) norms[(b * Hn + h) * Lsz + l] = ss;
}

// ---------------- exact top-k per (b,h): bitonic sort + tie handling -----------
__global__ void topk_kernel(const float* __restrict__ norms, int* __restrict__ sel) {
    int bh = blockIdx.x;
    __shared__ float s[Lsz];
    __shared__ int cnt_out;
    __shared__ int cnt_gt;
    const float* nb = norms + (size_t)bh * Lsz;
    int tid = threadIdx.x;
    for (int i = tid; i < Lsz; i += 256) s[i] = nb[i];
    __syncthreads();
    for (int ksz = 2; ksz <= Lsz; ksz <<= 1) {
        for (int j = ksz >> 1; j > 0; j >>= 1) {
            for (int idx = tid; idx < Lsz; idx += 256) {
                int ixj = idx ^ j;
                if (ixj > idx) {
                    bool desc = ((idx & ksz) == 0);
                    float a = s[idx], bb = s[ixj];
                    bool sw = desc ? (a < bb) : (a > bb);
                    if (sw) { s[idx] = bb; s[ixj] = a; }
                }
            }
            __syncthreads();
        }
    }
    float t = s[KTOPn - 1];
    if (tid == 0) { cnt_out = 0; cnt_gt = 0; }
    __syncthreads();
    int lc = 0;
    for (int i = tid; i < Lsz; i += 256) lc += (nb[i] > t) ? 1 : 0;
    atomicAdd(&cnt_gt, lc);
    __syncthreads();
    int need = KTOPn - cnt_gt;
    for (int i = tid; i < Lsz; i += 256) {
        float v = nb[i];
        bool pick = false;
        if (v > t) pick = true;
        else if (v == t) {
            int eqb = 0;
            for (int jj = 0; jj < i; jj++) eqb += (nb[jj] == t) ? 1 : 0;
            pick = (eqb < need);
        }
        if (pick) {
            int p = atomicAdd(&cnt_out, 1);
            sel[(size_t)bh * KTOPn + p] = i;
        }
    }
}

// ---------------- V column means -----------------------------------------------
__global__ void vpartial_kernel(const float* __restrict__ V, float* __restrict__ part) {
    int b = blockIdx.x >> 5, c = blockIdx.x & 31;
    int d = threadIdx.x;
    float sum = 0.f;
#pragma unroll 4
    for (int r = 0; r < 64; r++)
        sum += V[(size_t)(b * Lsz + c * 64 + r) * Dsz + d];
    part[(size_t)(b * 32 + c) * Dsz + d] = sum;
}

__global__ void vmean_kernel(const float* __restrict__ part, float* __restrict__ vm) {
    int i = blockIdx.x * 256 + threadIdx.x;
    if (i >= Bsz * Dsz) return;
    int b = i / Dsz, d = i % Dsz;
    float sum = 0.f;
#pragma unroll
    for (int c = 0; c < 32; c++) sum += part[(size_t)(b * 32 + c) * Dsz + d];
    vm[i] = sum * (1.0f / Lsz);
}

__global__ void fill_kernel(const float* __restrict__ vm, float* __restrict__ attn) {
    size_t i = (size_t)blockIdx.x * 256 + threadIdx.x;
    if (i >= (size_t)Bsz * Lsz * Dsz) return;
    int d = (int)(i % Dsz);
    int b = (int)(i / ((size_t)Lsz * Dsz));
    attn[i] = vm[b * Dsz + d];
}

// ------------- tensor-core flash attention over selected queries ---------------
// 128 threads (4 warps), 32 queries per block, 64-key tiles, m16n8k8 tf32.
// Scores: warps split keys (16 each). PV: warps split head-dim (16 each).
// Q fragments preloaded in registers (pre-scaled by 0.125, exact). Probs pass
// through smem (QP buffer reused after Q staging). Flash stats per-thread
// (4 rows each) with quad-shuffle + smem partial merges.
__global__ __launch_bounds__(128)
void attn_tc(const float* __restrict__ Q, const float* __restrict__ K,
             const float* __restrict__ V, const int* __restrict__ sel,
             float* __restrict__ out) {
    __shared__ float QP[32][68];      // Q staging, then probs
    __shared__ float Ks[64][68];
    __shared__ float Vs[64][68];
    __shared__ float pmax[4][32], psum[4][32];
    __shared__ int   sidx[32];

    int bh = blockIdx.y, b = bh / Hn, h = bh % Hn;
    int qbase = blockIdx.x * 32;
    int tid = threadIdx.x, wid = tid >> 5, lane = tid & 31;
    int group = lane >> 2, tg = lane & 3;
    int wb = wid * 16;

    if (tid < 32)
        sidx[tid] = (qbase + tid < KTOPn) ? sel[(size_t)bh * KTOPn + qbase + tid] : -1;
    __syncthreads();

    // stage selected Q rows, pre-scaled, tf32
    for (int i = tid; i < 32 * 16; i += 128) {
        int r = i >> 4, c4 = (i & 15) * 4;
        float4 v = make_float4(0.f, 0.f, 0.f, 0.f);
        int sl = sidx[r];
        if (sl >= 0) v = *(const float4*)&Q[(size_t)(b * Lsz + sl) * Dsz + h * HDs + c4];
        unsigned t0, t1, t2, t3;
        CVT_TF32(t0, v.x * SCALE); CVT_TF32(t1, v.y * SCALE);
        CVT_TF32(t2, v.z * SCALE); CVT_TF32(t3, v.w * SCALE);
        QP[r][c4+0] = __uint_as_float(t0); QP[r][c4+1] = __uint_as_float(t1);
        QP[r][c4+2] = __uint_as_float(t2); QP[r][c4+3] = __uint_as_float(t3);
    }
    __syncthreads();

    // preload Q fragments (fixed across all key tiles)
    unsigned aQ[2][8][4];
#pragma unroll
    for (int mt = 0; mt < 2; mt++)
#pragma unroll
        for (int ks = 0; ks < 8; ks++) {
            int row = mt * 16 + group, k = ks * 8;
            aQ[mt][ks][0] = __float_as_uint(QP[row][k + tg]);
            aQ[mt][ks][1] = __float_as_uint(QP[row + 8][k + tg]);
            aQ[mt][ks][2] = __float_as_uint(QP[row][k + tg + 4]);
            aQ[mt][ks][3] = __float_as_uint(QP[row + 8][k + tg + 4]);
        }
    __syncthreads();   // QP now free for probs

    float m_s[4] = { -INFINITY, -INFINITY, -INFINITY, -INFINITY };
    float l_s[4] = { 0.f, 0.f, 0.f, 0.f };
    float O[2][2][4];
#pragma unroll
    for (int mt = 0; mt < 2; mt++)
#pragma unroll
        for (int nt = 0; nt < 2; nt++)
#pragma unroll
            for (int i = 0; i < 4; i++) O[mt][nt][i] = 0.f;

    for (int kt = 0; kt < Lsz / 64; kt++) {
        __syncthreads();   // prior PV done with Ps/Vs; safe to reload
        for (int i = tid; i < 64 * 16; i += 128) {
            int r = i >> 4, c4 = (i & 15) * 4;
            size_t gro = (size_t)(b * Lsz + kt * 64 + r) * Dsz + h * HDs + c4;
            float4 kv = *(const float4*)&K[gro];
            float4 vv = *(const float4*)&V[gro];
            unsigned t0, t1, t2, t3;
            CVT_TF32(t0, kv.x); CVT_TF32(t1, kv.y); CVT_TF32(t2, kv.z); CVT_TF32(t3, kv.w);
            Ks[r][c4+0] = __uint_as_float(t0); Ks[r][c4+1] = __uint_as_float(t1);
            Ks[r][c4+2] = __uint_as_float(t2); Ks[r][c4+3] = __uint_as_float(t3);
            CVT_TF32(t0, vv.x); CVT_TF32(t1, vv.y); CVT_TF32(t2, vv.z); CVT_TF32(t3, vv.w);
            Vs[r][c4+0] = __uint_as_float(t0); Vs[r][c4+1] = __uint_as_float(t1);
            Vs[r][c4+2] = __uint_as_float(t2); Vs[r][c4+3] = __uint_as_float(t3);
        }
        __syncthreads();

        // scores: this warp's 16 keys
        float s[2][2][4];
#pragma unroll
        for (int mt = 0; mt < 2; mt++)
#pragma unroll
            for (int nt = 0; nt < 2; nt++)
#pragma unroll
                for (int i = 0; i < 4; i++) s[mt][nt][i] = 0.f;
#pragma unroll
        for (int nt = 0; nt < 2; nt++)
#pragma unroll
            for (int ks = 0; ks < 8; ks++) {
                int n = wb + nt * 8 + group, k = ks * 8;
                unsigned bb[2];
                bb[0] = __float_as_uint(Ks[n][k + tg]);
                bb[1] = __float_as_uint(Ks[n][k + tg + 4]);
                MMA_TF32(s[0][nt], aQ[0][ks], bb);
                MMA_TF32(s[1][nt], aQ[1][ks], bb);
            }

        // partial row max over this warp's 16 keys
        float lm[4];
#pragma unroll
        for (int mt = 0; mt < 2; mt++)
#pragma unroll
            for (int hh = 0; hh < 2; hh++) {
                float m = fmaxf(fmaxf(s[mt][0][hh*2], s[mt][0][hh*2+1]),
                                fmaxf(s[mt][1][hh*2], s[mt][1][hh*2+1]));
                m = fmaxf(m, __shfl_xor_sync(0xffffffffu, m, 1));
                m = fmaxf(m, __shfl_xor_sync(0xffffffffu, m, 2));
                lm[mt*2+hh] = m;
            }
        if (tg == 0) {
#pragma unroll
            for (int mt = 0; mt < 2; mt++)
#pragma unroll
                for (int hh = 0; hh < 2; hh++)
                    pmax[wid][mt*16 + hh*8 + group] = lm[mt*2+hh];
        }
        __syncthreads();

        float mnew[4], corr[4];
#pragma unroll
        for (int mt = 0; mt < 2; mt++)
#pragma unroll
            for (int hh = 0; hh < 2; hh++) {
                int r = mt*16 + hh*8 + group, idx = mt*2+hh;
                float g = fmaxf(fmaxf(pmax[0][r], pmax[1][r]),
                                fmaxf(pmax[2][r], pmax[3][r]));
                mnew[idx] = fmaxf(m_s[idx], g);
                corr[idx] = __expf(m_s[idx] - mnew[idx]);
                m_s[idx] = mnew[idx];
            }

        // probs (tf32) to smem + partial sums
        float ls[4] = { 0.f, 0.f, 0.f, 0.f };
#pragma unroll
        for (int mt = 0; mt < 2; mt++)
#pragma unroll
            for (int hh = 0; hh < 2; hh++) {
                int r = mt*16 + hh*8 + group, idx = mt*2+hh;
#pragma unroll
                for (int nt = 0; nt < 2; nt++) {
                    float p0 = __expf(s[mt][nt][hh*2]   - mnew[idx]);
                    float p1 = __expf(s[mt][nt][hh*2+1] - mnew[idx]);
                    unsigned u0, u1;
                    CVT_TF32(u0, p0); CVT_TF32(u1, p1);
                    int col = wb + nt*8 + tg*2;
                    QP[r][col]   = __uint_as_float(u0);
                    QP[r][col+1] = __uint_as_float(u1);
                    ls[idx] += p0 + p1;
                }
            }
#pragma unroll
        for (int idx = 0; idx < 4; idx++) {
            float v = ls[idx];
            v += __shfl_xor_sync(0xffffffffu, v, 1);
            v += __shfl_xor_sync(0xffffffffu, v, 2);
            ls[idx] = v;
        }
        if (tg == 0) {
#pragma unroll
            for (int mt = 0; mt < 2; mt++)
#pragma unroll
                for (int hh = 0; hh < 2; hh++)
                    psum[wid][mt*16 + hh*8 + group] = ls[mt*2+hh];
        }
        __syncthreads();

#pragma unroll
        for (int mt = 0; mt < 2; mt++)
#pragma unroll
            for (int hh = 0; hh < 2; hh++) {
                int r = mt*16 + hh*8 + group, idx = mt*2+hh;
                float ts = psum[0][r] + psum[1][r] + psum[2][r] + psum[3][r];
                l_s[idx] = l_s[idx] * corr[idx] + ts;
            }

        // rescale O, then PV over all 64 keys for this warp's 16 hd cols
#pragma unroll
        for (int mt = 0; mt < 2; mt++)
#pragma unroll
            for (int nt = 0; nt < 2; nt++) {
                O[mt][nt][0] *= corr[mt*2];   O[mt][nt][1] *= corr[mt*2];
                O[mt][nt][2] *= corr[mt*2+1]; O[mt][nt][3] *= corr[mt*2+1];
            }
#pragma unroll
        for (int ks = 0; ks < 8; ks++) {
            int k = ks * 8;
            unsigned aP[2][4];
#pragma unroll
            for (int mt = 0; mt < 2; mt++) {
                int row = mt*16 + group;
                aP[mt][0] = __float_as_uint(QP[row][k + tg]);
                aP[mt][1] = __float_as_uint(QP[row + 8][k + tg]);
                aP[mt][2] = __float_as_uint(QP[row][k + tg + 4]);
                aP[mt][3] = __float_as_uint(QP[row + 8][k + tg + 4]);
            }
#pragma unroll
            for (int nt = 0; nt < 2; nt++) {
                unsigned bb[2];
                bb[0] = __float_as_uint(Vs[k + tg][wb + nt*8 + group]);
                bb[1] = __float_as_uint(Vs[k + tg + 4][wb + nt*8 + group]);
                MMA_TF32(O[0][nt], aP[0], bb);
                MMA_TF32(O[1][nt], aP[1], bb);
            }
        }
    }

    // write normalized output rows
#pragma unroll
    for (int mt = 0; mt < 2; mt++)
#pragma unroll
        for (int hh = 0; hh < 2; hh++) {
            int r = mt*16 + hh*8 + group, idx = mt*2+hh;
            if (qbase + r < KTOPn) {
                int sl = sidx[r];
                float inv = 1.0f / l_s[idx];
#pragma unroll
                for (int nt = 0; nt < 2; nt++) {
                    int col = h * HDs + wb + nt*8 + tg*2;
                    *(float2*)&out[(size_t)(b * Lsz + sl) * Dsz + col] =
                        make_float2(O[mt][nt][hh*2] * inv, O[mt][nt][hh*2+1] * inv);
                }
            }
        }
}

// ---------------- launch -------------------------------------------------------
extern "C" void kernel_launch(void* const* d_in, const int* in_sizes, int n_in,
                              void* d_out, int out_size) {
    const float* x  = (const float*)d_in[0];
    const float* Wq = (const float*)d_in[1];
    const float* bq = (const float*)d_in[2];
    const float* Wk = (const float*)d_in[3];
    const float* bk = (const float*)d_in[4];
    const float* Wv = (const float*)d_in[5];
    const float* bv = (const float*)d_in[6];
    const float* Wo = (const float*)d_in[7];
    const float* bo = (const float*)d_in[8];
    float* out = (float*)d_out;

    float *pQ, *pK, *pV, *pA, *pN, *pPart, *pM;
    int* pS;
    cudaGetSymbolAddress((void**)&pQ, g_Q);
    cudaGetSymbolAddress((void**)&pK, g_K);
    cudaGetSymbolAddress((void**)&pV, g_V);
    cudaGetSymbolAddress((void**)&pA, g_A);
    cudaGetSymbolAddress((void**)&pN, g_norm);
    cudaGetSymbolAddress((void**)&pS, g_sel);
    cudaGetSymbolAddress((void**)&pPart, g_part);
    cudaGetSymbolAddress((void**)&pM, g_vmean);

    const int M = Bsz * Lsz;   // 4096
    dim3 gemm_grid(Dsz / 128, M / 128);

    gemm_3xtf32<<<gemm_grid, 256>>>(x, Wq, bq, pQ, M, Dsz, Dsz);
    gemm_1xtf32<<<gemm_grid, 256>>>(x, Wk, bk, pK, M, Dsz, Dsz);
    gemm_1xtf32<<<gemm_grid, 256>>>(x, Wv, bv, pV, M, Dsz, Dsz);

    qnorm_kernel<<<(BHn * Lsz) / 8, 256>>>(pQ, pN);
    topk_kernel<<<BHn, 256>>>(pN, pS);

    vpartial_kernel<<<Bsz * 32, 1024>>>(pV, pPart);
    vmean_kernel<<<(Bsz * Dsz + 255) / 256, 256>>>(pPart, pM);
    fill_kernel<<<(Bsz * Lsz * Dsz) / 256, 256>>>(pM, pA);

    attn_tc<<<dim3((KTOPn + 31) / 32, BHn), 128>>>(pQ, pK, pV, pS, pA);

    gemm_1xtf32<<<gemm_grid, 256>>>(pA, Wo, bo, out, M, Dsz, Dsz);
}